// round 1
// baseline (speedup 1.0000x reference)
#include <cuda_runtime.h>
#include <cstdint>

#define TDIM 1024
#define HDIM 2048
#define IDIM 5632
#define NEXP 8
#define TOPK 2
#define NROWS (TDIM * TOPK)       // 2048 routed rows
#define N1 (2 * IDIM)             // 11264 (gate+up)
#define BM 128
#define BN 128
#define BK 32
#define BKP 36                    // padded K stride (bank-conflict free, 16B aligned)
#define MAXTILES 24               // sum_e ceil(n_e/128) <= 2048/128 + 8 = 24

// ---------------- scratch (device globals: no allocations allowed) ----------
__device__ int   g_row_token[NROWS];
__device__ float g_row_weight[NROWS];
__device__ int   g_row_slot[NROWS];
__device__ int   g_tile_expert[MAXTILES];
__device__ int   g_tile_rowstart[MAXTILES];
__device__ int   g_tile_rowcnt[MAXTILES];
__device__ int   g_ntiles;
__device__ float g_h13[(size_t)NROWS * N1];       // 88 MB
__device__ float g_act[(size_t)NROWS * IDIM];     // 44 MB
__device__ float g_partial[(size_t)NROWS * HDIM]; // 16 MB

// ---------------- routing ---------------------------------------------------
__global__ void route_kernel(const int* __restrict__ ids, const float* __restrict__ w)
{
    __shared__ int cnt[NEXP];
    __shared__ int off[NEXP];
    __shared__ int cur[NEXP];
    int tid = threadIdx.x;
    if (tid < NEXP) cnt[tid] = 0;
    __syncthreads();
    for (int a = tid; a < NROWS; a += blockDim.x)
        atomicAdd(&cnt[ids[a]], 1);
    __syncthreads();
    if (tid == 0) {
        int s = 0;
        for (int e = 0; e < NEXP; e++) { off[e] = s; cur[e] = s; s += cnt[e]; }
        int nt = 0;
        for (int e = 0; e < NEXP; e++) {
            for (int r = 0; r < cnt[e]; r += BM) {
                g_tile_expert[nt]   = e;
                g_tile_rowstart[nt] = off[e] + r;
                g_tile_rowcnt[nt]   = min(BM, cnt[e] - r);
                nt++;
            }
        }
        g_ntiles = nt;
    }
    __syncthreads();
    for (int a = tid; a < NROWS; a += blockDim.x) {
        int e = ids[a];
        int pos = atomicAdd(&cur[e], 1);
        g_row_token[pos]  = a / TOPK;
        g_row_weight[pos] = w[a];
        g_row_slot[pos]   = a;      // t*TOPK + k
    }
}

// ---------------- tf32 helpers ----------------------------------------------
__device__ __forceinline__ uint32_t f2tf32(float x)
{
    uint32_t r;
    asm("cvt.rna.tf32.f32 %0, %1;" : "=r"(r) : "f"(x));
    return r;
}

__device__ __forceinline__ void mma_tf32(float (&d)[4],
                                         const uint32_t (&a)[4],
                                         const uint32_t (&b)[2])
{
    asm volatile(
        "mma.sync.aligned.m16n8k8.row.col.f32.tf32.tf32.f32 "
        "{%0,%1,%2,%3}, {%4,%5,%6,%7}, {%8,%9}, {%0,%1,%2,%3};\n"
        : "+f"(d[0]), "+f"(d[1]), "+f"(d[2]), "+f"(d[3])
        : "r"(a[0]), "r"(a[1]), "r"(a[2]), "r"(a[3]),
          "r"(b[0]), "r"(b[1]));
}

// ---------------- grouped GEMM (tf32 mma.sync, 128x128x32) ------------------
// G2=false: h13[r, n] = sum_h hidden[token[r], h] * w13[e, n, h]  (KDIM=H, NTOT=2I)
// G2=true : partial[slot[r], n] = w[r] * sum_i act[r, i] * w2[e, n, i] (KDIM=I, NTOT=H)
template<int KDIM, int NTOT, bool G2>
__global__ __launch_bounds__(256)
void moe_gemm_kernel(const float* __restrict__ Asrc,
                     const float* __restrict__ Bsrc)
{
    const int tile = blockIdx.x;
    if (tile >= g_ntiles) return;
    const int e        = g_tile_expert[tile];
    const int rowstart = g_tile_rowstart[tile];
    const int rowcnt   = g_tile_rowcnt[tile];
    const int nbase    = blockIdx.y * BN;

    extern __shared__ uint32_t smem[];
    uint32_t* sA = smem;                 // [2][BM][BKP]
    uint32_t* sB = smem + 2 * BM * BKP;  // [2][BN][BKP]

    const float* A = G2 ? (const float*)g_act : Asrc;
    float*       C = G2 ? g_partial : g_h13;

    const int tid  = threadIdx.x;
    const int lrow = tid >> 3;           // 0..31
    const int lcol = (tid & 7) * 4;      // 0..28, step 4

    // per-thread source pointers for the 4 row chunks it stages
    const float* aPtr[4];
    const float* bPtr[4];
    const float* Bexp = Bsrc + (size_t)e * NTOT * KDIM;
#pragma unroll
    for (int i = 0; i < 4; i++) {
        int r  = lrow + i * 32;
        int re = r < rowcnt ? r : rowcnt - 1;   // clamp padded rows (loads only)
        if (G2) aPtr[i] = A + (size_t)(rowstart + re) * KDIM + lcol;
        else    aPtr[i] = A + (size_t)g_row_token[rowstart + re] * KDIM + lcol;
        bPtr[i] = Bexp + (size_t)(nbase + r) * KDIM + lcol;
    }

    const int lane = tid & 31;
    const int g    = lane >> 2;
    const int tig  = lane & 3;
    const int warp = tid >> 5;
    const int wm   = (warp & 1) * 64;    // warp m-offset (2 warps in M)
    const int wn   = (warp >> 1) * 32;   // warp n-offset (4 warps in N)

    float acc[4][4][4];
#pragma unroll
    for (int mt = 0; mt < 4; mt++)
#pragma unroll
        for (int nt = 0; nt < 4; nt++)
#pragma unroll
            for (int i = 0; i < 4; i++) acc[mt][nt][i] = 0.f;

    const int KITER = KDIM / BK;
    float4 aReg[4], bReg[4];

    // prologue: stage tile 0
#pragma unroll
    for (int i = 0; i < 4; i++) {
        aReg[i] = *(const float4*)(aPtr[i]);
        bReg[i] = *(const float4*)(bPtr[i]);
    }
#pragma unroll
    for (int i = 0; i < 4; i++) {
        uint4 va, vb;
        va.x = f2tf32(aReg[i].x); va.y = f2tf32(aReg[i].y);
        va.z = f2tf32(aReg[i].z); va.w = f2tf32(aReg[i].w);
        vb.x = f2tf32(bReg[i].x); vb.y = f2tf32(bReg[i].y);
        vb.z = f2tf32(bReg[i].z); vb.w = f2tf32(bReg[i].w);
        *(uint4*)&sA[(lrow + i * 32) * BKP + lcol] = va;
        *(uint4*)&sB[(lrow + i * 32) * BKP + lcol] = vb;
    }
    __syncthreads();

    int buf = 0;
    for (int kt = 0; kt < KITER; kt++) {
        // issue next tile's global loads early (latency hidden under mma)
        if (kt + 1 < KITER) {
#pragma unroll
            for (int i = 0; i < 4; i++) {
                aReg[i] = *(const float4*)(aPtr[i] + (size_t)(kt + 1) * BK);
                bReg[i] = *(const float4*)(bPtr[i] + (size_t)(kt + 1) * BK);
            }
        }

        const uint32_t* cA = sA + buf * BM * BKP;
        const uint32_t* cB = sB + buf * BM * BKP;
#pragma unroll
        for (int ks = 0; ks < 4; ks++) {
            const int kk = ks * 8;
            uint32_t af[4][4], bf[4][2];
#pragma unroll
            for (int mt = 0; mt < 4; mt++) {
                int m0 = wm + mt * 16;
                af[mt][0] = cA[(m0 + g    ) * BKP + kk + tig];
                af[mt][1] = cA[(m0 + g + 8) * BKP + kk + tig];
                af[mt][2] = cA[(m0 + g    ) * BKP + kk + tig + 4];
                af[mt][3] = cA[(m0 + g + 8) * BKP + kk + tig + 4];
            }
#pragma unroll
            for (int nt = 0; nt < 4; nt++) {
                int n0 = wn + nt * 8;
                bf[nt][0] = cB[(n0 + g) * BKP + kk + tig];
                bf[nt][1] = cB[(n0 + g) * BKP + kk + tig + 4];
            }
#pragma unroll
            for (int mt = 0; mt < 4; mt++)
#pragma unroll
                for (int nt = 0; nt < 4; nt++)
                    mma_tf32(acc[mt][nt], af[mt], bf[nt]);
        }

        if (kt + 1 < KITER) {
            int nb = buf ^ 1;
            uint32_t* dA = sA + nb * BM * BKP;
            uint32_t* dB = sB + nb * BM * BKP;
#pragma unroll
            for (int i = 0; i < 4; i++) {
                uint4 va, vb;
                va.x = f2tf32(aReg[i].x); va.y = f2tf32(aReg[i].y);
                va.z = f2tf32(aReg[i].z); va.w = f2tf32(aReg[i].w);
                vb.x = f2tf32(bReg[i].x); vb.y = f2tf32(bReg[i].y);
                vb.z = f2tf32(bReg[i].z); vb.w = f2tf32(bReg[i].w);
                *(uint4*)&dA[(lrow + i * 32) * BKP + lcol] = va;
                *(uint4*)&dB[(lrow + i * 32) * BKP + lcol] = vb;
            }
            buf = nb;
        }
        __syncthreads();
    }

    // epilogue
#pragma unroll
    for (int mt = 0; mt < 4; mt++) {
        int r0 = wm + mt * 16 + g;
#pragma unroll
        for (int half = 0; half < 2; half++) {
            int r = r0 + half * 8;
            if (r < rowcnt) {
                int gr = rowstart + r;
                size_t base;
                float wgt = 1.f;
                if (G2) {
                    base = (size_t)g_row_slot[gr] * HDIM + nbase;
                    wgt  = g_row_weight[gr];
                } else {
                    base = (size_t)gr * (size_t)N1 + nbase;
                }
#pragma unroll
                for (int nt = 0; nt < 4; nt++) {
                    int c = wn + nt * 8 + 2 * tig;
                    float2 v;
                    v.x = acc[mt][nt][half * 2 + 0] * wgt;
                    v.y = acc[mt][nt][half * 2 + 1] * wgt;
                    *(float2*)&C[base + c] = v;
                }
            }
        }
    }
}

// ---------------- SwiGLU -----------------------------------------------------
__global__ void swiglu_kernel()
{
    size_t idx = (size_t)blockIdx.x * blockDim.x + threadIdx.x;   // exact cover
    size_t r = idx / IDIM;
    size_t i = idx - r * IDIM;
    float v = g_h13[r * (size_t)N1 + i];
    float u = g_h13[r * (size_t)N1 + IDIM + i];
    float s = v / (1.f + __expf(-v));
    g_act[r * (size_t)IDIM + i] = s * u;
}

// ---------------- combine (atomic-free, deterministic) ----------------------
__global__ void combine_kernel(float* __restrict__ out)
{
    size_t idx = (size_t)blockIdx.x * blockDim.x + threadIdx.x;   // T*H
    size_t t = idx / HDIM;
    out[idx] = g_partial[idx + t * HDIM] + g_partial[idx + t * HDIM + HDIM];
}

// ---------------- launch -----------------------------------------------------
extern "C" void kernel_launch(void* const* d_in, const int* in_sizes, int n_in,
                              void* d_out, int out_size)
{
    const float* hidden = (const float*)d_in[0];
    const int*   ids    = (const int*)d_in[1];
    const float* wts    = (const float*)d_in[2];
    // d_in[3] = router_logits (unused: topk already materialized)
    const float* w13    = (const float*)d_in[4];
    const float* w2     = (const float*)d_in[5];
    float* out = (float*)d_out;

    const int smem_bytes = 4 * BM * BKP * (int)sizeof(uint32_t);  // 73728 B
    cudaFuncSetAttribute(moe_gemm_kernel<HDIM, N1, false>,
                         cudaFuncAttributeMaxDynamicSharedMemorySize, smem_bytes);
    cudaFuncSetAttribute(moe_gemm_kernel<IDIM, HDIM, true>,
                         cudaFuncAttributeMaxDynamicSharedMemorySize, smem_bytes);

    route_kernel<<<1, 256>>>(ids, wts);

    moe_gemm_kernel<HDIM, N1, false>
        <<<dim3(MAXTILES, N1 / BN), 256, smem_bytes>>>(hidden, w13);

    swiglu_kernel<<<(int)(((size_t)NROWS * IDIM) / 256), 256>>>();

    moe_gemm_kernel<IDIM, HDIM, true>
        <<<dim3(MAXTILES, HDIM / BN), 256, smem_bytes>>>(nullptr, w2);

    combine_kernel<<<(int)(((size_t)TDIM * HDIM) / 256), 256>>>(out);
}